// round 1
// baseline (speedup 1.0000x reference)
#include <cuda_runtime.h>
#include <cuda_bf16.h>
#include <math.h>

// Problem shape (fixed by the dataset)
#define NROWS 32768
#define HDIM  1024

// 128 MB scratch for the hidden activations (reused for h1 and h3).
__device__ float g_h[(size_t)NROWS * HDIM];
__device__ float g_rowsum[HDIM];
__device__ float g_rowsq[HDIM];

// ---------------------------------------------------------------------------
// Codebook per-row stats: row_sum[i] = sum_j C[i][j], row_sqsum[i] = sum_j C[i][j]^2
// One block per codebook row.
// ---------------------------------------------------------------------------
__global__ __launch_bounds__(256)
void cb_stats_kernel(const float* __restrict__ cb,
                     float* __restrict__ rowsum,
                     float* __restrict__ rowsq)
{
    const int i   = blockIdx.x;
    const int tid = threadIdx.x;
    const float* row = cb + (size_t)i * HDIM;

    float s = 0.f, q = 0.f;
    #pragma unroll
    for (int j = tid; j < HDIM; j += 256) {
        float v = row[j];
        s += v;
        q = fmaf(v, v, q);
    }

    __shared__ float ss[256];
    __shared__ float qq[256];
    ss[tid] = s; qq[tid] = q;
    __syncthreads();
    for (int off = 128; off > 0; off >>= 1) {
        if (tid < off) {
            ss[tid] += ss[tid + off];
            qq[tid] += qq[tid + off];
        }
        __syncthreads();
    }
    if (tid == 0) {
        rowsum[i] = ss[0];
        rowsq[i]  = qq[0];
    }
}

// ---------------------------------------------------------------------------
// VQ: per row n, argmin_i ( H*z^2 - 2*z*row_sum[i] + row_sqsum[i] ), z = z_e[n][i]
// then gather z_q[n][:] = codebook[idx][:].
// One block of 256 threads per row. Lowest-index tie-break (matches jnp.argmin).
// ---------------------------------------------------------------------------
__global__ __launch_bounds__(256)
void vq_kernel(const float* __restrict__ ze,
               const float* __restrict__ cb,
               const float* __restrict__ rowsum,
               const float* __restrict__ rowsq,
               float* __restrict__ zq)
{
    const int n   = blockIdx.x;
    const int tid = threadIdx.x;
    const float* z = ze + (size_t)n * HDIM;

    float best = INFINITY;
    int   bidx = 0x7fffffff;
    #pragma unroll
    for (int j = 0; j < 4; j++) {
        int i = tid + j * 256;
        float zv = z[i];
        float d  = fmaf(1024.0f * zv, zv, fmaf(-2.0f * zv, rowsum[i], rowsq[i]));
        if (d < best || (d == best && i < bidx)) { best = d; bidx = i; }
    }

    __shared__ float sd[256];
    __shared__ int   si[256];
    sd[tid] = best; si[tid] = bidx;
    __syncthreads();
    for (int off = 128; off > 0; off >>= 1) {
        if (tid < off) {
            float d2 = sd[tid + off];
            int   i2 = si[tid + off];
            if (d2 < sd[tid] || (d2 == sd[tid] && i2 < si[tid])) {
                sd[tid] = d2; si[tid] = i2;
            }
        }
        __syncthreads();
    }
    const int idx = si[0];

    // Gather codebook row -> z_q (256 threads x float4 = 1024 floats).
    const float4* src = reinterpret_cast<const float4*>(cb + (size_t)idx * HDIM);
    float4*       dst = reinterpret_cast<float4*>(zq + (size_t)n * HDIM);
    dst[tid] = src[tid];
}

// ---------------------------------------------------------------------------
// Fused GEMM + bias + activation.
// C[M,N] = act(A[M,K] @ B[K,N] + bias[N])
// BM=BN=128, BK=8, 256 threads, 8x8 per thread. All dims multiples of 128/8.
// EPI: 0 = ReLU, 1 = sigmoid.
// ---------------------------------------------------------------------------
template<int EPI>
__device__ __forceinline__ float epi_act(float v) {
    if (EPI == 0) return fmaxf(v, 0.0f);
    else          return 1.0f / (1.0f + expf(-v));
}

template<int EPI>
__global__ __launch_bounds__(256)
void sgemm_epi(const float* __restrict__ A, const float* __restrict__ B,
               const float* __restrict__ bias, float* __restrict__ C,
               int M, int N, int K)
{
    __shared__ float As[8][128];
    __shared__ float Bs[8][132];   // padded

    const int tid = threadIdx.x;
    const int bx  = blockIdx.x;    // N tile
    const int by  = blockIdx.y;    // M tile

    // A tile loader: 128 rows x 8 k's = 256 float4 (one per thread, along K)
    const int a_row = tid >> 1;
    const int a_col = (tid & 1) << 2;
    // B tile loader: 8 rows x 128 cols = 256 float4
    const int b_row = tid >> 5;
    const int b_col = (tid & 31) << 2;

    const int tx = tid & 15;       // 0..15 -> 8 cols each
    const int ty = tid >> 4;       // 0..15 -> 8 rows each

    const float* Ap = A + (size_t)(by * 128 + a_row) * K + a_col;
    const float* Bp = B + (size_t)b_row * N + bx * 128 + b_col;

    float acc[8][8];
    #pragma unroll
    for (int i = 0; i < 8; i++)
        #pragma unroll
        for (int j = 0; j < 8; j++) acc[i][j] = 0.f;

    for (int k0 = 0; k0 < K; k0 += 8) {
        float4 av = *reinterpret_cast<const float4*>(Ap);
        float4 bv = *reinterpret_cast<const float4*>(Bp);
        Ap += 8;
        Bp += (size_t)8 * N;

        As[a_col + 0][a_row] = av.x;
        As[a_col + 1][a_row] = av.y;
        As[a_col + 2][a_row] = av.z;
        As[a_col + 3][a_row] = av.w;
        *reinterpret_cast<float4*>(&Bs[b_row][b_col]) = bv;
        __syncthreads();

        #pragma unroll
        for (int kk = 0; kk < 8; kk++) {
            float a[8], b[8];
            #pragma unroll
            for (int i = 0; i < 8; i++) a[i] = As[kk][ty * 8 + i];
            #pragma unroll
            for (int j = 0; j < 8; j++) b[j] = Bs[kk][tx * 8 + j];
            #pragma unroll
            for (int i = 0; i < 8; i++)
                #pragma unroll
                for (int j = 0; j < 8; j++)
                    acc[i][j] = fmaf(a[i], b[j], acc[i][j]);
        }
        __syncthreads();
    }

    // Epilogue: bias + activation, float4 stores.
    const int colbase = bx * 128 + tx * 8;
    float bb[8];
    #pragma unroll
    for (int j = 0; j < 8; j++) bb[j] = bias[colbase + j];

    #pragma unroll
    for (int i = 0; i < 8; i++) {
        const size_t row = (size_t)(by * 128 + ty * 8 + i);
        float* Cp = C + row * N + colbase;
        float4 v0, v1;
        v0.x = epi_act<EPI>(acc[i][0] + bb[0]);
        v0.y = epi_act<EPI>(acc[i][1] + bb[1]);
        v0.z = epi_act<EPI>(acc[i][2] + bb[2]);
        v0.w = epi_act<EPI>(acc[i][3] + bb[3]);
        v1.x = epi_act<EPI>(acc[i][4] + bb[4]);
        v1.y = epi_act<EPI>(acc[i][5] + bb[5]);
        v1.z = epi_act<EPI>(acc[i][6] + bb[6]);
        v1.w = epi_act<EPI>(acc[i][7] + bb[7]);
        *reinterpret_cast<float4*>(Cp + 0) = v0;
        *reinterpret_cast<float4*>(Cp + 4) = v1;
    }
}

// ---------------------------------------------------------------------------
// Launch
// ---------------------------------------------------------------------------
extern "C" void kernel_launch(void* const* d_in, const int* in_sizes, int n_in,
                              void* d_out, int out_size)
{
    const float* x  = (const float*)d_in[0];
    const float* W1 = (const float*)d_in[1];
    const float* b1 = (const float*)d_in[2];
    const float* W2 = (const float*)d_in[3];
    const float* b2 = (const float*)d_in[4];
    const float* cb = (const float*)d_in[5];
    const float* W3 = (const float*)d_in[6];
    const float* b3 = (const float*)d_in[7];
    const float* W4 = (const float*)d_in[8];
    const float* b4 = (const float*)d_in[9];

    float* out = (float*)d_out;
    const int N = NROWS, H = HDIM, D = HDIM;

    float* x_recon = out;                          // (N, D)
    float* z_e     = out + (size_t)N * D;          // (N, H)
    float* z_q     = z_e + (size_t)N * H;          // (N, H)

    float* h;  cudaGetSymbolAddress((void**)&h,  g_h);
    float* rs; cudaGetSymbolAddress((void**)&rs, g_rowsum);
    float* rq; cudaGetSymbolAddress((void**)&rq, g_rowsq);

    dim3 gg(H / 128, N / 128);
    dim3 blk(256);

    // encoder
    sgemm_epi<0><<<gg, blk>>>(x, W1, b1, h,   N, H, D);   // h1 = relu(x@W1+b1)
    sgemm_epi<0><<<gg, blk>>>(h, W2, b2, z_e, N, H, H);   // z_e = relu(h1@W2+b2)

    // VQ
    cb_stats_kernel<<<HDIM, 256>>>(cb, rs, rq);
    vq_kernel<<<N, 256>>>(z_e, cb, rs, rq, z_q);

    // decoder
    sgemm_epi<0><<<gg, blk>>>(z_q, W3, b3, h,       N, H, H);  // h3 = relu(z_q@W3+b3)
    sgemm_epi<1><<<gg, blk>>>(h,   W4, b4, x_recon, N, D, H);  // x_recon = sigmoid(h3@W4+b4)
}

// round 3
// speedup vs baseline: 3.1930x; 3.1930x over previous
#include <cuda_runtime.h>
#include <cuda_bf16.h>
#include <math.h>
#include <stdint.h>

#define NROWS 32768
#define HD    1024

// ---------------------------------------------------------------------------
// Scratch (device globals; no allocations allowed)
// ---------------------------------------------------------------------------
__device__ __nv_bfloat16 g_ahi[(size_t)NROWS * HD];
__device__ __nv_bfloat16 g_alo[(size_t)NROWS * HD];
__device__ __nv_bfloat16 g_bhi[(size_t)NROWS * HD];
__device__ __nv_bfloat16 g_blo[(size_t)NROWS * HD];
__device__ __nv_bfloat16 g_wthi[4][(size_t)HD * HD];
__device__ __nv_bfloat16 g_wtlo[4][(size_t)HD * HD];
__device__ float g_rowsum[HD];
__device__ float g_rowsq[HD];

// ---------------------------------------------------------------------------
// PTX helpers (sm_80-era instructions only — no 'a'-suffix features, since the
// harness compiles the PTX stage for plain compute_103)
// ---------------------------------------------------------------------------
__device__ __forceinline__ uint32_t smem_to_u32(const void* p) {
    uint32_t a;
    asm("{ .reg .u64 t; cvta.to.shared.u64 t, %1; cvt.u32.u64 %0, t; }" : "=r"(a) : "l"(p));
    return a;
}
#define CP_ASYNC16(dst, src) \
    asm volatile("cp.async.cg.shared.global [%0], [%1], 16;" :: "r"(dst), "l"(src))
#define CP_COMMIT() asm volatile("cp.async.commit_group;" ::: "memory")
#define CP_WAIT1()  asm volatile("cp.async.wait_group 1;" ::: "memory")
#define CP_WAIT0()  asm volatile("cp.async.wait_group 0;" ::: "memory")

#define LDSM4(r0, r1, r2, r3, addr) \
    asm volatile("ldmatrix.sync.aligned.m8n8.x4.shared.b16 {%0,%1,%2,%3}, [%4];" \
        : "=r"(r0), "=r"(r1), "=r"(r2), "=r"(r3) : "r"(addr))

#define MMA16816(d, a, b) \
    asm volatile("mma.sync.aligned.m16n8k16.row.col.f32.bf16.bf16.f32 " \
        "{%0,%1,%2,%3}, {%4,%5,%6,%7}, {%8,%9}, {%0,%1,%2,%3};" \
        : "+f"((d)[0]), "+f"((d)[1]), "+f"((d)[2]), "+f"((d)[3]) \
        : "r"((a)[0]), "r"((a)[1]), "r"((a)[2]), "r"((a)[3]), \
          "r"((b)[0]), "r"((b)[1]))

__device__ __forceinline__ void split1(float v, __nv_bfloat16& h, __nv_bfloat16& l) {
    h = __float2bfloat16(v);
    l = __float2bfloat16(v - __bfloat162float(h));
}

// ---------------------------------------------------------------------------
// Prep kernels
// ---------------------------------------------------------------------------
__global__ __launch_bounds__(256)
void split_act(const float4* __restrict__ x, __nv_bfloat162* __restrict__ hi,
               __nv_bfloat162* __restrict__ lo)
{
    size_t i = (size_t)blockIdx.x * 256 + threadIdx.x;
    float4 v = x[i];
    __nv_bfloat16 h0,l0,h1,l1,h2,l2,h3,l3;
    split1(v.x,h0,l0); split1(v.y,h1,l1); split1(v.z,h2,l2); split1(v.w,h3,l3);
    __nv_bfloat162 a,b;
    a.x=h0; a.y=h1; b.x=h2; b.y=h3;
    hi[2*i]=a; hi[2*i+1]=b;
    a.x=l0; a.y=l1; b.x=l2; b.y=l3;
    lo[2*i]=a; lo[2*i+1]=b;
}

// transpose+split weights: W[K,N] fp32 -> Wt[N,K] bf16 hi/lo
__global__ __launch_bounds__(1024)
void wsplit_t(const float* __restrict__ W, __nv_bfloat16* __restrict__ hi,
              __nv_bfloat16* __restrict__ lo)
{
    __shared__ float s[32][33];
    int n0 = blockIdx.x * 32, k0 = blockIdx.y * 32;
    s[threadIdx.y][threadIdx.x] = W[(size_t)(k0 + threadIdx.y) * HD + n0 + threadIdx.x];
    __syncthreads();
    float v = s[threadIdx.x][threadIdx.y];
    int n = n0 + threadIdx.y, k = k0 + threadIdx.x;
    __nv_bfloat16 h, l; split1(v, h, l);
    hi[(size_t)n * HD + k] = h;
    lo[(size_t)n * HD + k] = l;
}

__global__ __launch_bounds__(256)
void cb_stats_kernel(const float* __restrict__ cb, float* __restrict__ rowsum,
                     float* __restrict__ rowsq)
{
    const int i = blockIdx.x, tid = threadIdx.x;
    const float* row = cb + (size_t)i * HD;
    float s = 0.f, q = 0.f;
    for (int j = tid; j < HD; j += 256) { float v = row[j]; s += v; q = fmaf(v, v, q); }
    __shared__ float ss[256], qq[256];
    ss[tid] = s; qq[tid] = q;
    __syncthreads();
    for (int off = 128; off > 0; off >>= 1) {
        if (tid < off) { ss[tid] += ss[tid+off]; qq[tid] += qq[tid+off]; }
        __syncthreads();
    }
    if (tid == 0) { rowsum[i] = ss[0]; rowsq[i] = qq[0]; }
}

// ---------------------------------------------------------------------------
// VQ: argmin + gather (fp32 out + split-bf16 out for next GEMM)
// ---------------------------------------------------------------------------
__global__ __launch_bounds__(256)
void vq_kernel(const float* __restrict__ ze, const float* __restrict__ cb,
               const float* __restrict__ rowsum, const float* __restrict__ rowsq,
               float* __restrict__ zq, __nv_bfloat16* __restrict__ zqh,
               __nv_bfloat16* __restrict__ zql)
{
    const int n = blockIdx.x, tid = threadIdx.x;
    const float* z = ze + (size_t)n * HD;
    float best = INFINITY; int bidx = 0x7fffffff;
    #pragma unroll
    for (int j = 0; j < 4; j++) {
        int i = tid + j * 256;
        float zv = z[i];
        float d = fmaf(1024.0f * zv, zv, fmaf(-2.0f * zv, rowsum[i], rowsq[i]));
        if (d < best || (d == best && i < bidx)) { best = d; bidx = i; }
    }
    __shared__ float sd[256]; __shared__ int si[256];
    sd[tid] = best; si[tid] = bidx;
    __syncthreads();
    for (int off = 128; off > 0; off >>= 1) {
        if (tid < off) {
            float d2 = sd[tid+off]; int i2 = si[tid+off];
            if (d2 < sd[tid] || (d2 == sd[tid] && i2 < si[tid])) { sd[tid]=d2; si[tid]=i2; }
        }
        __syncthreads();
    }
    const int idx = si[0];
    float4 v = reinterpret_cast<const float4*>(cb + (size_t)idx * HD)[tid];
    reinterpret_cast<float4*>(zq + (size_t)n * HD)[tid] = v;
    __nv_bfloat16 h0,l0,h1,l1,h2,l2,h3,l3;
    split1(v.x,h0,l0); split1(v.y,h1,l1); split1(v.z,h2,l2); split1(v.w,h3,l3);
    __nv_bfloat162 a,b;
    __nv_bfloat162* ph = reinterpret_cast<__nv_bfloat162*>(zqh + (size_t)n * HD);
    __nv_bfloat162* pl = reinterpret_cast<__nv_bfloat162*>(zql + (size_t)n * HD);
    a.x=h0; a.y=h1; b.x=h2; b.y=h3; ph[2*tid]=a; ph[2*tid+1]=b;
    a.x=l0; a.y=l1; b.x=l2; b.y=l3; pl[2*tid]=a; pl[2*tid+1]=b;
}

// ---------------------------------------------------------------------------
// mma.sync split-bf16 GEMM: C[M,1024] = act(A @ W + bias)
//   A as Ahi/Alo [M,1024] bf16 (row-major, K contiguous)
//   W as Whi/Wlo [N,K] = W^T bf16 (row-major == B col-major for mma .col)
// CTA tile 256x128, 512 threads (16 warps, 64x32 warp tiles), KC=64,
// double-buffered cp.async, SW128 xor swizzle.
// C = Ahi*Bhi + Ahi*Blo + Alo*Bhi  (3-term split, err ~2^-16)
// EPI: 0=relu, 1=sigmoid.  MODE: 0=fp32 C, 1=split bf16 Chi/Clo.
// ---------------------------------------------------------------------------
#define BM 256
#define BN 128
#define KC 64
#define NKI (HD / KC)      // 16
#define THREADS 512

#define AHI_OFF 0
#define ALO_OFF 32768
#define BHI_OFF 65536
#define BLO_OFF 81920
#define STAGE_B 98304
#define SMEM_TOTAL (2 * STAGE_B)   // 196608

__device__ __forceinline__ void load_stage(
    uint32_t sdst,
    const __nv_bfloat16* __restrict__ Ahi, const __nv_bfloat16* __restrict__ Alo,
    const __nv_bfloat16* __restrict__ Bhi, const __nv_bfloat16* __restrict__ Blo,
    int mbase, int nbase, int c, int tid)
{
    const int kel = c * KC;   // k offset in elements
    #pragma unroll
    for (int i = 0; i < 4; ++i) {           // A hi: 2048 chunks
        int id = tid + i * THREADS;
        int row = id >> 3, u = id & 7;
        const char* src = (const char*)(Ahi + (size_t)(mbase + row) * HD + kel + u * 8);
        uint32_t dst = sdst + AHI_OFF + row * 128 + ((u ^ (row & 7)) << 4);
        CP_ASYNC16(dst, src);
    }
    #pragma unroll
    for (int i = 0; i < 4; ++i) {           // A lo
        int id = tid + i * THREADS;
        int row = id >> 3, u = id & 7;
        const char* src = (const char*)(Alo + (size_t)(mbase + row) * HD + kel + u * 8);
        uint32_t dst = sdst + ALO_OFF + row * 128 + ((u ^ (row & 7)) << 4);
        CP_ASYNC16(dst, src);
    }
    #pragma unroll
    for (int i = 0; i < 2; ++i) {           // B hi: 1024 chunks
        int id = tid + i * THREADS;
        int row = id >> 3, u = id & 7;
        const char* src = (const char*)(Bhi + (size_t)(nbase + row) * HD + kel + u * 8);
        uint32_t dst = sdst + BHI_OFF + row * 128 + ((u ^ (row & 7)) << 4);
        CP_ASYNC16(dst, src);
    }
    #pragma unroll
    for (int i = 0; i < 2; ++i) {           // B lo
        int id = tid + i * THREADS;
        int row = id >> 3, u = id & 7;
        const char* src = (const char*)(Blo + (size_t)(nbase + row) * HD + kel + u * 8);
        uint32_t dst = sdst + BLO_OFF + row * 128 + ((u ^ (row & 7)) << 4);
        CP_ASYNC16(dst, src);
    }
}

template<int EPI, int MODE>
__global__ __launch_bounds__(THREADS, 1)
void gemm_mma(const __nv_bfloat16* __restrict__ Ahi, const __nv_bfloat16* __restrict__ Alo,
              const __nv_bfloat16* __restrict__ Bhi, const __nv_bfloat16* __restrict__ Blo,
              const float* __restrict__ bias,
              float* __restrict__ Cf,
              __nv_bfloat16* __restrict__ Chi, __nv_bfloat16* __restrict__ Clo)
{
    extern __shared__ char smem[];
    const uint32_t sb = smem_to_u32(smem);
    const int tid  = threadIdx.x;
    const int wid  = tid >> 5;
    const int lane = tid & 31;
    const int wm = wid & 3;                 // 0..3 (m), warp tile row = wm*64
    const int wn = wid >> 2;                // 0..3 (n), warp tile col = wn*32
    const int mbase = blockIdx.y * BM;
    const int nbase = blockIdx.x * BN;

    float acc[4][4][4];
    #pragma unroll
    for (int i = 0; i < 4; i++)
        #pragma unroll
        for (int j = 0; j < 4; j++)
            #pragma unroll
            for (int k = 0; k < 4; k++) acc[i][j][k] = 0.f;

    // fragment addressing (constant per thread)
    const int a_row_l = lane & 15;          // row within m16 tile
    const int a_half  = lane >> 4;          // k half (0/1)
    const int b_n_l   = (lane & 7) + ((lane >> 4) << 3);  // n within n16
    const int b_half  = (lane >> 3) & 1;    // k half

    load_stage(sb, Ahi, Alo, Bhi, Blo, mbase, nbase, 0, tid);
    CP_COMMIT();

    for (int c = 0; c < NKI; ++c) {
        if (c + 1 < NKI) {
            load_stage(sb + ((c + 1) & 1) * STAGE_B, Ahi, Alo, Bhi, Blo,
                       mbase, nbase, c + 1, tid);
            CP_COMMIT();
            CP_WAIT1();
        } else {
            CP_WAIT0();
        }
        __syncthreads();

        const uint32_t st = sb + (c & 1) * STAGE_B;
        #pragma unroll
        for (int ks = 0; ks < 4; ++ks) {
            uint32_t ah[4][4], bh[4][2], bl[4][2];
            // A hi fragments (4 m-tiles)
            #pragma unroll
            for (int i = 0; i < 4; ++i) {
                int row = wm * 64 + i * 16 + a_row_l;
                int u = ks * 2 + a_half;
                uint32_t addr = st + AHI_OFF + row * 128 + ((u ^ (row & 7)) << 4);
                LDSM4(ah[i][0], ah[i][1], ah[i][2], ah[i][3], addr);
            }
            // B hi fragments (4 n-tiles via 2 x4 loads)
            #pragma unroll
            for (int jj = 0; jj < 2; ++jj) {
                int n = wn * 32 + jj * 16 + b_n_l;
                int u = ks * 2 + b_half;
                uint32_t addr = st + BHI_OFF + n * 128 + ((u ^ (n & 7)) << 4);
                LDSM4(bh[jj*2][0], bh[jj*2][1], bh[jj*2+1][0], bh[jj*2+1][1], addr);
            }
            #pragma unroll
            for (int i = 0; i < 4; ++i)
                #pragma unroll
                for (int j = 0; j < 4; ++j)
                    MMA16816(acc[i][j], ah[i], bh[j]);

            // B lo fragments -> Ahi * Blo
            #pragma unroll
            for (int jj = 0; jj < 2; ++jj) {
                int n = wn * 32 + jj * 16 + b_n_l;
                int u = ks * 2 + b_half;
                uint32_t addr = st + BLO_OFF + n * 128 + ((u ^ (n & 7)) << 4);
                LDSM4(bl[jj*2][0], bl[jj*2][1], bl[jj*2+1][0], bl[jj*2+1][1], addr);
            }
            #pragma unroll
            for (int i = 0; i < 4; ++i)
                #pragma unroll
                for (int j = 0; j < 4; ++j)
                    MMA16816(acc[i][j], ah[i], bl[j]);

            // A lo fragments (reuse ah regs) -> Alo * Bhi
            #pragma unroll
            for (int i = 0; i < 4; ++i) {
                int row = wm * 64 + i * 16 + a_row_l;
                int u = ks * 2 + a_half;
                uint32_t addr = st + ALO_OFF + row * 128 + ((u ^ (row & 7)) << 4);
                LDSM4(ah[i][0], ah[i][1], ah[i][2], ah[i][3], addr);
            }
            #pragma unroll
            for (int i = 0; i < 4; ++i)
                #pragma unroll
                for (int j = 0; j < 4; ++j)
                    MMA16816(acc[i][j], ah[i], bh[j]);
        }
        __syncthreads();
    }

    // Epilogue: bias + activation, direct stores.
    #pragma unroll
    for (int j = 0; j < 4; ++j) {
        const int col = nbase + wn * 32 + j * 8 + (lane & 3) * 2;
        const float2 bj = *reinterpret_cast<const float2*>(bias + col);
        #pragma unroll
        for (int i = 0; i < 4; ++i) {
            const int r0 = mbase + wm * 64 + i * 16 + (lane >> 2);
            const int r1 = r0 + 8;
            float v0 = acc[i][j][0] + bj.x;
            float v1 = acc[i][j][1] + bj.y;
            float v2 = acc[i][j][2] + bj.x;
            float v3 = acc[i][j][3] + bj.y;
            if (EPI == 0) {
                v0 = fmaxf(v0, 0.f); v1 = fmaxf(v1, 0.f);
                v2 = fmaxf(v2, 0.f); v3 = fmaxf(v3, 0.f);
            } else {
                v0 = 1.f / (1.f + expf(-v0)); v1 = 1.f / (1.f + expf(-v1));
                v2 = 1.f / (1.f + expf(-v2)); v3 = 1.f / (1.f + expf(-v3));
            }
            if (MODE == 0) {
                float2 p0 = {v0, v1}, p1 = {v2, v3};
                *reinterpret_cast<float2*>(Cf + (size_t)r0 * HD + col) = p0;
                *reinterpret_cast<float2*>(Cf + (size_t)r1 * HD + col) = p1;
            } else {
                __nv_bfloat16 h0,l0,h1,l1,h2,l2,h3,l3;
                split1(v0,h0,l0); split1(v1,h1,l1); split1(v2,h2,l2); split1(v3,h3,l3);
                __nv_bfloat162 hh0; hh0.x=h0; hh0.y=h1;
                __nv_bfloat162 ll0; ll0.x=l0; ll0.y=l1;
                __nv_bfloat162 hh1; hh1.x=h2; hh1.y=h3;
                __nv_bfloat162 ll1; ll1.x=l2; ll1.y=l3;
                *reinterpret_cast<__nv_bfloat162*>(Chi + (size_t)r0 * HD + col) = hh0;
                *reinterpret_cast<__nv_bfloat162*>(Clo + (size_t)r0 * HD + col) = ll0;
                *reinterpret_cast<__nv_bfloat162*>(Chi + (size_t)r1 * HD + col) = hh1;
                *reinterpret_cast<__nv_bfloat162*>(Clo + (size_t)r1 * HD + col) = ll1;
            }
        }
    }
}

// ---------------------------------------------------------------------------
// Launch
// ---------------------------------------------------------------------------
extern "C" void kernel_launch(void* const* d_in, const int* in_sizes, int n_in,
                              void* d_out, int out_size)
{
    const float* x  = (const float*)d_in[0];
    const float* W1 = (const float*)d_in[1];
    const float* b1 = (const float*)d_in[2];
    const float* W2 = (const float*)d_in[3];
    const float* b2 = (const float*)d_in[4];
    const float* cb = (const float*)d_in[5];
    const float* W3 = (const float*)d_in[6];
    const float* b3 = (const float*)d_in[7];
    const float* W4 = (const float*)d_in[8];
    const float* b4 = (const float*)d_in[9];

    float* out = (float*)d_out;
    float* x_recon = out;
    float* z_e = out + (size_t)NROWS * HD;
    float* z_q = z_e + (size_t)NROWS * HD;

    __nv_bfloat16 *ahi, *alo, *bhi, *blo, *wh, *wl;
    float *rs, *rq;
    cudaGetSymbolAddress((void**)&ahi, g_ahi);
    cudaGetSymbolAddress((void**)&alo, g_alo);
    cudaGetSymbolAddress((void**)&bhi, g_bhi);
    cudaGetSymbolAddress((void**)&blo, g_blo);
    cudaGetSymbolAddress((void**)&wh,  g_wthi);
    cudaGetSymbolAddress((void**)&wl,  g_wtlo);
    cudaGetSymbolAddress((void**)&rs,  g_rowsum);
    cudaGetSymbolAddress((void**)&rq,  g_rowsq);
    const size_t WSZ = (size_t)HD * HD;

    cudaFuncSetAttribute(gemm_mma<0,1>, cudaFuncAttributeMaxDynamicSharedMemorySize, SMEM_TOTAL);
    cudaFuncSetAttribute(gemm_mma<0,0>, cudaFuncAttributeMaxDynamicSharedMemorySize, SMEM_TOTAL);
    cudaFuncSetAttribute(gemm_mma<1,0>, cudaFuncAttributeMaxDynamicSharedMemorySize, SMEM_TOTAL);

    // ---- prep: split x, transpose+split weights, codebook stats ----
    split_act<<<(NROWS * HD / 4) / 256, 256>>>((const float4*)x,
        (__nv_bfloat162*)ahi, (__nv_bfloat162*)alo);
    dim3 tb(32, 32), tg(HD / 32, HD / 32);
    wsplit_t<<<tg, tb>>>(W1, wh + 0 * WSZ, wl + 0 * WSZ);
    wsplit_t<<<tg, tb>>>(W2, wh + 1 * WSZ, wl + 1 * WSZ);
    wsplit_t<<<tg, tb>>>(W3, wh + 2 * WSZ, wl + 2 * WSZ);
    wsplit_t<<<tg, tb>>>(W4, wh + 3 * WSZ, wl + 3 * WSZ);
    cb_stats_kernel<<<HD, 256>>>(cb, rs, rq);

    dim3 gg(HD / BN, NROWS / BM);   // (8, 128)
    dim3 blk(THREADS);

    // encoder
    gemm_mma<0,1><<<gg, blk, SMEM_TOTAL>>>(ahi, alo, wh + 0*WSZ, wl + 0*WSZ, b1,
                                           nullptr, bhi, blo);            // h1 (split)
    gemm_mma<0,0><<<gg, blk, SMEM_TOTAL>>>(bhi, blo, wh + 1*WSZ, wl + 1*WSZ, b2,
                                           z_e, nullptr, nullptr);        // z_e fp32

    // VQ (writes z_q fp32 + split into ahi/alo)
    vq_kernel<<<NROWS, 256>>>(z_e, cb, rs, rq, z_q, ahi, alo);

    // decoder
    gemm_mma<0,1><<<gg, blk, SMEM_TOTAL>>>(ahi, alo, wh + 2*WSZ, wl + 2*WSZ, b3,
                                           nullptr, bhi, blo);            // h3 (split)
    gemm_mma<1,0><<<gg, blk, SMEM_TOTAL>>>(bhi, blo, wh + 3*WSZ, wl + 3*WSZ, b4,
                                           x_recon, nullptr, nullptr);    // x_recon fp32
}